// round 2
// baseline (speedup 1.0000x reference)
#include <cuda_runtime.h>

#define POOLP 7
#define NCHAN 256

__global__ __launch_bounds__(512, 2) void roi_pool(
    const float* __restrict__ p2, const float* __restrict__ p3,
    const float* __restrict__ p4, const float* __restrict__ p5,
    const float* __restrict__ rois,
    float* __restrict__ out)
{
    int n  = blockIdx.x;
    int pt   = threadIdx.x & 63;   // sample point within 7x7 (49 active)
    int cofs = threadIdx.x >> 6;   // channel group 0..7
    if (pt >= 49) return;

    // ---- per-roi params (uniform broadcast loads) ----
    float rx1 = __ldg(rois + 4 * n + 0);
    float ry1 = __ldg(rois + 4 * n + 1);
    float rx2 = __ldg(rois + 4 * n + 2);
    float ry2 = __ldg(rois + 4 * n + 3);

    // level = clip(round(log2(sqrt(area)/224)) + 4, 2, 5)   (rintf = half-even, matches jnp.round)
    float area = (ry2 - ry1) * (rx2 - rx1);
    float lvlf = log2f(sqrtf(fmaxf(area, 0.0f)) / 224.0f);
    int level = (int)rintf(lvlf) + 4;
    level = min(5, max(2, level));

    int W  = 1024 >> level;            // H == W: 256,128,64,32
    int hw = W * W;
    float scale = (float)(W - 1);

    const float* fm = (level == 2) ? p2
                    : (level == 3) ? p3
                    : (level == 4) ? p4 : p5;

    // normalized (y1,x1,y2,x2) = rois[:,[1,0,3,2]] / 1024
    float ny1 = ry1 * (1.0f / 1024.0f);
    float nx1 = rx1 * (1.0f / 1024.0f);
    float ny2 = ry2 * (1.0f / 1024.0f);
    float nx2 = rx2 * (1.0f / 1024.0f);
    float dy = __fsub_rn(ny2, ny1);
    float dx = __fsub_rn(nx2, nx1);

    int py = pt / 7;
    int px = pt - py * 7;

    // ---- y sample (explicit rn ops: (ny1 + t*dy) * (H-1), matches reference) ----
    float ty = (float)py / 6.0f;
    float ys = __fmul_rn(__fadd_rn(ny1, __fmul_rn(ty, dy)), scale);
    bool  vy = (ys >= 0.0f) && (ys <= scale);
    float ysc = fminf(fmaxf(ys, 0.0f), scale);
    int   y0  = (int)floorf(ysc);
    int   y1i = min(y0 + 1, W - 1);
    float ly  = __fsub_rn(ysc, (float)y0);

    // ---- x sample ----
    float tx = (float)px / 6.0f;
    float xs = __fmul_rn(__fadd_rn(nx1, __fmul_rn(tx, dx)), scale);
    bool  vx = (xs >= 0.0f) && (xs <= scale);
    float xsc = fminf(fmaxf(xs, 0.0f), scale);
    int   x0  = (int)floorf(xsc);
    float lx  = __fsub_rn(xsc, (float)x0);

    float m  = (vy && vx) ? 1.0f : 0.0f;

    // ---- fold mask + x-weights into an aligned-quad weight pattern ----
    // quad covers columns [x0&~3 .. x0&~3+3]; s = position of x0 in the quad.
    // tl weight = m*(1-lx) at s, tr weight = m*lx at s+1 (s==3 spills to wextra).
    // Note: when x0 == W-1, lx == 0, so the tr weight is 0 and clamping is moot.
    int   s  = x0 & 3;
    int   qx = x0 & ~3;
    int offA = y0  * W + qx;
    int offB = y1i * W + qx;
    float wl = m * (1.0f - lx);
    float wr = m * lx;
    float4 pat;
    pat.x = (s == 0) ? wl : 0.0f;
    pat.y = (s == 1) ? wl : ((s == 0) ? wr : 0.0f);
    pat.z = (s == 2) ? wl : ((s == 1) ? wr : 0.0f);
    pat.w = (s == 3) ? wl : ((s == 2) ? wr : 0.0f);
    float wextra = (s == 3) ? wr : 0.0f;
    // If wextra != 0 then lx != 0 => x0+1 <= W-1, and offA+4 == y0*W + x0+1 (in-row).

    int obase = n * (NCHAN * 49) + pt;

    if (wextra == 0.0f) {
        #pragma unroll 4
        for (int c = cofs; c < NCHAN; c += 8) {
            const float* fc = fm + c * hw;
            float4 qA = __ldg((const float4*)(fc + offA));
            float4 qB = __ldg((const float4*)(fc + offB));
            float rA = qA.x * pat.x + qA.y * pat.y + qA.z * pat.z + qA.w * pat.w;
            float rB = qB.x * pat.x + qB.y * pat.y + qB.z * pat.z + qB.w * pat.w;
            out[obase + c * 49] = fmaf(rB - rA, ly, rA);
        }
    } else {
        #pragma unroll 4
        for (int c = cofs; c < NCHAN; c += 8) {
            const float* fc = fm + c * hw;
            float4 qA = __ldg((const float4*)(fc + offA));
            float4 qB = __ldg((const float4*)(fc + offB));
            float eA = __ldg(fc + offA + 4);
            float eB = __ldg(fc + offB + 4);
            float rA = qA.x * pat.x + qA.y * pat.y + qA.z * pat.z + qA.w * pat.w + eA * wextra;
            float rB = qB.x * pat.x + qB.y * pat.y + qB.z * pat.z + qB.w * pat.w + eB * wextra;
            out[obase + c * 49] = fmaf(rB - rA, ly, rA);
        }
    }
}

extern "C" void kernel_launch(void* const* d_in, const int* in_sizes, int n_in,
                              void* d_out, int out_size) {
    const float* p2   = (const float*)d_in[0];
    const float* p3   = (const float*)d_in[1];
    const float* p4   = (const float*)d_in[2];
    const float* p5   = (const float*)d_in[3];
    const float* rois = (const float*)d_in[4];
    float* out = (float*)d_out;

    int nrois = in_sizes[4] / 4;   // B*R
    roi_pool<<<nrois, 512>>>(p2, p3, p4, p5, rois, out);
}